// round 7
// baseline (speedup 1.0000x reference)
#include <cuda_runtime.h>

// ---------------------------------------------------------------------------
// GINDeepSigns: N=20000 nodes, K=4 eigs (8 signed copies), E=320000 edges,
// H=64, OUT=16.
//   h0[i,c] = +/- x[i, c%4]                          (scalar feature)
//   conv l: z = h + A@h  (A = dst<-src adjacency);   h' = relu(z@W1+b1)@W2+b2
//   pool:   p[i,:] = 0.25 * sum_c h[i,c,:]
//   out  = relu(p@rW1+rb1)@rW2+rb2
// Strategy: on-device edge-index dtype probe (int32 vs int64), per-launch CSR
// build (histogram/scan/scatter), then coalesced warp-per-node gather
// aggregation + thread-per-row register-accumulator MLPs.
// All state ping-pongs between two 41MB __device__ buffers (L2-resident).
// ---------------------------------------------------------------------------

#define NN 20000
#define NEDGE 320000
#define RCOP 8
#define HD 64
#define ROWF (RCOP * HD)      // 512 floats per node
#define R8 (NN * RCOP)        // 160000 rows

__device__ __align__(16) float g_bufA[R8 * HD];
__device__ __align__(16) float g_bufB[R8 * HD];
__device__ __align__(16) float g_pool[NN * HD];
__device__ __align__(16) float g_tmp[NN * HD];
__device__ int g_rowstart[NN + 1];
__device__ int g_cursor[NN];
__device__ int g_csr[NEDGE];
__device__ int g_bsums[64];
__device__ int g_is64;

__device__ __forceinline__ float4 f4add(float4 a, float4 b) {
    a.x += b.x; a.y += b.y; a.z += b.z; a.w += b.w; return a;
}
__device__ __forceinline__ float4 f4fma(float s, float4 w, float4 a) {
    a.x = fmaf(s, w.x, a.x); a.y = fmaf(s, w.y, a.y);
    a.z = fmaf(s, w.z, a.z); a.w = fmaf(s, w.w, a.w); return a;
}

// Decode edge_index element `pos` regardless of whether the buffer holds
// int64 or int32 values. Clamp to valid node range (turns any residual
// mismatch into a wrong answer instead of an illegal access).
__device__ __forceinline__ int load_idx(const void* ei, int pos) {
    int v;
    if (g_is64) v = (int)((const long long*)ei)[pos];
    else        v = ((const int*)ei)[pos];
    return min(max(v, 0), NN - 1);
}

// ---------------- dtype probe ----------------------------------------------
// If the buffer is little-endian int64 with values < 2^31, every odd 32-bit
// word is zero. If it's int32, odd words are random node ids (>0 w.p. ~1).
__global__ void k_detect(const int* __restrict__ ei32) {
    __shared__ int s_any;
    if (threadIdx.x == 0) s_any = 0;
    __syncthreads();
    int any = 0;
    for (int i = threadIdx.x; i < 4096; i += blockDim.x) any |= ei32[2 * i + 1];
    if (any) atomicOr(&s_any, 1);
    __syncthreads();
    if (threadIdx.x == 0) g_is64 = (s_any == 0) ? 1 : 0;
}

// ---------------- CSR build -------------------------------------------------

__global__ void k_zero() {
    int idx = blockIdx.x * blockDim.x + threadIdx.x;
    if (idx <= NN) g_rowstart[idx] = 0;
    if (idx < NN)  g_cursor[idx]   = 0;
}

__global__ void k_count(const void* __restrict__ ei) {
    int e = blockIdx.x * blockDim.x + threadIdx.x;
    if (e >= NEDGE) return;
    int d = load_idx(ei, NEDGE + e);
    atomicAdd(&g_rowstart[d + 1], 1);
}

__global__ void k_scan1() {  // per-512-block inclusive scan
    __shared__ int sh[512];
    int tid = threadIdx.x;
    int idx = blockIdx.x * 512 + tid;
    int v = (idx <= NN) ? g_rowstart[idx] : 0;
    sh[tid] = v; __syncthreads();
    for (int off = 1; off < 512; off <<= 1) {
        int t = (tid >= off) ? sh[tid - off] : 0;
        __syncthreads();
        sh[tid] += t; __syncthreads();
    }
    if (idx <= NN) g_rowstart[idx] = sh[tid];
    if (tid == 511) g_bsums[blockIdx.x] = sh[511];
}

__global__ void k_scan2() {  // exclusive scan of 40 block sums
    __shared__ int sh[64];
    int tid = threadIdx.x;
    int v = (tid < 40) ? g_bsums[tid] : 0;
    sh[tid] = v; __syncthreads();
    for (int off = 1; off < 64; off <<= 1) {
        int t = (tid >= off) ? sh[tid - off] : 0;
        __syncthreads();
        sh[tid] += t; __syncthreads();
    }
    if (tid < 40) g_bsums[tid] = sh[tid] - v;
}

__global__ void k_scan3() {
    int idx = blockIdx.x * blockDim.x + threadIdx.x;
    if (idx <= NN) g_rowstart[idx] += g_bsums[idx >> 9];
}

__global__ void k_scatter(const void* __restrict__ ei) {
    int e = blockIdx.x * blockDim.x + threadIdx.x;
    if (e >= NEDGE) return;
    int s = load_idx(ei, e);
    int d = load_idx(ei, NEDGE + e);
    int pos = atomicAdd(&g_cursor[d], 1);
    int slot = g_rowstart[d] + pos;
    if (slot >= 0 && slot < NEDGE) g_csr[slot] = s;
}

// ---------------- conv0: scalar feature, fused agg + MLP --------------------

__global__ void k_conv0(const float* __restrict__ x,
                        const float* __restrict__ W1, const float* __restrict__ b1,
                        const float* __restrict__ W2, const float* __restrict__ b2,
                        float* __restrict__ out) {
    __shared__ __align__(16) float sW1[64], sb1[64], sW2[64 * 64], sb2[64];
    int tid = threadIdx.x;
    for (int t = tid; t < 64 * 64; t += blockDim.x) sW2[t] = W2[t];
    if (tid < 64) { sW1[tid] = W1[tid]; sb1[tid] = b1[tid]; sb2[tid] = b2[tid]; }
    __syncthreads();

    int idx = blockIdx.x * blockDim.x + tid;
    if (idx >= R8) return;
    int i = idx >> 3, c = idx & 7, k = c & 3;

    float s = x[i * 4 + k];
    int e0 = g_rowstart[i], e1 = g_rowstart[i + 1];
    for (int e = e0; e < e1; e++) s += x[g_csr[e] * 4 + k];
    if (c >= 4) s = -s;   // sign factors out of the linear aggregation

    float4 acc[16];
#pragma unroll
    for (int j = 0; j < 16; j++) acc[j] = ((const float4*)sb2)[j];
#pragma unroll 4
    for (int m = 0; m < 64; m++) {
        float ym = fmaxf(fmaf(s, sW1[m], sb1[m]), 0.0f);
        const float4* w = (const float4*)(sW2 + m * 64);
#pragma unroll
        for (int j = 0; j < 16; j++) acc[j] = f4fma(ym, w[j], acc[j]);
    }
    float4* o = (float4*)(out + (size_t)idx * 64);
#pragma unroll
    for (int j = 0; j < 16; j++) o[j] = acc[j];
}

// ---------------- aggregation: warp per node, coalesced 2KB row gather ------

__global__ void k_agg(const float* __restrict__ h, float* __restrict__ z) {
    int gw   = (blockIdx.x * blockDim.x + threadIdx.x) >> 5;
    int lane = threadIdx.x & 31;
    if (gw >= NN) return;
    const float4* self = (const float4*)(h + (size_t)gw * ROWF);
    float4 a0 = self[lane], a1 = self[32 + lane], a2 = self[64 + lane], a3 = self[96 + lane];
    int e0 = g_rowstart[gw], e1 = g_rowstart[gw + 1];
    for (int e = e0; e < e1; e++) {
        const float4* src = (const float4*)(h + (size_t)g_csr[e] * ROWF);
        float4 v0 = src[lane], v1 = src[32 + lane], v2 = src[64 + lane], v3 = src[96 + lane];
        a0 = f4add(a0, v0); a1 = f4add(a1, v1); a2 = f4add(a2, v2); a3 = f4add(a3, v3);
    }
    float4* zo = (float4*)(z + (size_t)gw * ROWF);
    zo[lane] = a0; zo[32 + lane] = a1; zo[64 + lane] = a2; zo[96 + lane] = a3;
}

// ---------------- dense layer: thread per row, acc in regs, W in smem -------

template <int OUTD, bool RELU>
__global__ void k_mlp(const float* __restrict__ in, const float* __restrict__ W,
                      const float* __restrict__ b, float* __restrict__ out, int R) {
    __shared__ __align__(16) float sW[64 * OUTD];
    __shared__ __align__(16) float sb[OUTD];
    for (int t = threadIdx.x; t < 64 * OUTD; t += blockDim.x) sW[t] = W[t];
    for (int t = threadIdx.x; t < OUTD; t += blockDim.x) sb[t] = b[t];
    __syncthreads();

    int row = blockIdx.x * blockDim.x + threadIdx.x;
    if (row >= R) return;

    float4 acc[OUTD / 4];
#pragma unroll
    for (int j = 0; j < OUTD / 4; j++) acc[j] = ((const float4*)sb)[j];

    const float4* ir = (const float4*)(in + (size_t)row * 64);
#pragma unroll
    for (int kk = 0; kk < 16; kk++) {
        float4 f = ir[kk];
        float zs[4] = {f.x, f.y, f.z, f.w};
#pragma unroll
        for (int u = 0; u < 4; u++) {
            float zk = zs[u];
            const float4* w = (const float4*)(sW + (kk * 4 + u) * OUTD);
#pragma unroll
            for (int j = 0; j < OUTD / 4; j++) acc[j] = f4fma(zk, w[j], acc[j]);
        }
    }
    float4* o = (float4*)(out + (size_t)row * OUTD);
#pragma unroll
    for (int j = 0; j < OUTD / 4; j++) {
        float4 a = acc[j];
        if (RELU) {
            a.x = fmaxf(a.x, 0.0f); a.y = fmaxf(a.y, 0.0f);
            a.z = fmaxf(a.z, 0.0f); a.w = fmaxf(a.w, 0.0f);
        }
        o[j] = a;
    }
}

// ---------------- sign-invariant pool: mean over copies ---------------------

__global__ void k_pool(const float* __restrict__ h, float* __restrict__ p) {
    int idx = blockIdx.x * blockDim.x + threadIdx.x;
    if (idx >= NN * 16) return;
    int i = idx >> 4, q = idx & 15;
    const float4* base = (const float4*)(h + (size_t)i * ROWF);
    float4 s = make_float4(0.f, 0.f, 0.f, 0.f);
#pragma unroll
    for (int c = 0; c < 8; c++) s = f4add(s, base[c * 16 + q]);
    s.x *= 0.25f; s.y *= 0.25f; s.z *= 0.25f; s.w *= 0.25f;
    ((float4*)(p + (size_t)i * 64))[q] = s;
}

// ---------------------------------------------------------------------------

extern "C" void kernel_launch(void* const* d_in, const int* in_sizes, int n_in,
                              void* d_out, int out_size) {
    const float* x  = (const float*)d_in[0];
    const void*  ei = d_in[1];   // int32 or int64, probed on device
    const float* c0W1 = (const float*)d_in[2];
    const float* c0b1 = (const float*)d_in[3];
    const float* c0W2 = (const float*)d_in[4];
    const float* c0b2 = (const float*)d_in[5];
    const float* c1W1 = (const float*)d_in[6];
    const float* c1b1 = (const float*)d_in[7];
    const float* c1W2 = (const float*)d_in[8];
    const float* c1b2 = (const float*)d_in[9];
    const float* c2W1 = (const float*)d_in[10];
    const float* c2b1 = (const float*)d_in[11];
    const float* c2W2 = (const float*)d_in[12];
    const float* c2b2 = (const float*)d_in[13];
    const float* rW1  = (const float*)d_in[14];
    const float* rb1  = (const float*)d_in[15];
    const float* rW2  = (const float*)d_in[16];
    const float* rb2  = (const float*)d_in[17];
    float* out = (float*)d_out;

    float *A, *B, *P, *Q;
    cudaGetSymbolAddress((void**)&A, g_bufA);
    cudaGetSymbolAddress((void**)&B, g_bufB);
    cudaGetSymbolAddress((void**)&P, g_pool);
    cudaGetSymbolAddress((void**)&Q, g_tmp);

    // dtype probe + CSR build (per launch; graph-capturable, deterministic)
    k_detect<<<1, 256>>>((const int*)ei);
    k_zero<<<(NN + 256) / 256, 256>>>();
    k_count<<<NEDGE / 256, 256>>>(ei);
    k_scan1<<<40, 512>>>();
    k_scan2<<<1, 64>>>();
    k_scan3<<<(NN + 256) / 256, 256>>>();
    k_scatter<<<NEDGE / 256, 256>>>(ei);

    // conv0 (scalar in-feature, fused)
    k_conv0<<<R8 / 256, 256>>>(x, c0W1, c0b1, c0W2, c0b2, A);

    // conv1
    k_agg<<<NN / 8, 256>>>(A, B);
    k_mlp<64, true ><<<R8 / 256, 256>>>(B, c1W1, c1b1, A, R8);
    k_mlp<64, false><<<R8 / 256, 256>>>(A, c1W2, c1b2, B, R8);

    // conv2
    k_agg<<<NN / 8, 256>>>(B, A);
    k_mlp<64, true ><<<R8 / 256, 256>>>(A, c2W1, c2b1, B, R8);
    k_mlp<64, false><<<R8 / 256, 256>>>(B, c2W2, c2b2, A, R8);

    // pool + rho
    k_pool<<<(NN * 16) / 256, 256>>>(A, P);
    k_mlp<64, true ><<<(NN + 255) / 256, 256>>>(P, rW1, rb1, Q, NN);
    k_mlp<16, false><<<(NN + 255) / 256, 256>>>(Q, rW2, rb2, out, NN);
}